// round 2
// baseline (speedup 1.0000x reference)
#include <cuda_runtime.h>
#include <cuda_bf16.h>
#include <math.h>
#include <stdint.h>

#define BB 256
#define SS 15
#define HH 512
#define VV 50257

// Scratch (device globals: no allocation allowed)
__device__ float g_u[BB * HH];        // attn_W^T @ h  per batch
__device__ float g_x[BB * 2 * HH];    // [embedded ; context]
__device__ float g_gi[BB * 3 * HH];
__device__ float g_gh[BB * 3 * HH];
__device__ float g_hnew[BB * HH];
__device__ float g_lse[BB];

__device__ __forceinline__ float to_tf32(float x) {
    float y;
    asm("cvt.rna.tf32.f32 %0, %1;" : "=f"(y) : "f"(x));
    return y;
}

__device__ __forceinline__ void mma_tf32(float* d, const uint32_t* a, const uint32_t* b) {
    asm volatile(
        "mma.sync.aligned.m16n8k8.row.col.f32.tf32.tf32.f32 "
        "{%0,%1,%2,%3},{%4,%5,%6,%7},{%8,%9},{%0,%1,%2,%3};\n"
        : "+f"(d[0]), "+f"(d[1]), "+f"(d[2]), "+f"(d[3])
        : "r"(a[0]), "r"(a[1]), "r"(a[2]), "r"(a[3]), "r"(b[0]), "r"(b[1]));
}

// ---------------------------------------------------------------------------
// u[b,j] = sum_o h[b,o] * attn_W[o,j]   (fp32; attention path must be exact)
// grid (16, 4), block 128: 16 batches x 128 cols per block
// ---------------------------------------------------------------------------
__global__ void __launch_bounds__(128) u_kernel(const float* __restrict__ h,
                                                const float* __restrict__ W) {
    __shared__ float hs[16][HH];
    int mb = blockIdx.x * 16;
    int j = blockIdx.y * 128 + threadIdx.x;
    for (int i = threadIdx.x; i < 16 * HH; i += 128)
        hs[i / HH][i % HH] = h[(size_t)(mb + i / HH) * HH + (i % HH)];
    __syncthreads();
    float acc[16];
#pragma unroll
    for (int m = 0; m < 16; m++) acc[m] = 0.f;
    for (int o = 0; o < HH; o++) {
        float w = W[(size_t)o * HH + j];
#pragma unroll
        for (int m = 0; m < 16; m++) acc[m] = fmaf(hs[m][o], w, acc[m]);
    }
#pragma unroll
    for (int m = 0; m < 16; m++) g_u[(size_t)(mb + m) * HH + j] = acc[m];
}

// ---------------------------------------------------------------------------
// Per-batch: scores -> softmax -> attn_weights out, context, x = [emb ; ctx]
// grid (256), block 256. (h . attn_b) is constant per batch -> cancels in softmax.
// ---------------------------------------------------------------------------
__global__ void __launch_bounds__(256) attn_kernel(const float* __restrict__ enc,
                                                   const int* __restrict__ tok,
                                                   const float* __restrict__ emb,
                                                   float* __restrict__ attn_out) {
    int b = blockIdx.x;
    int t = threadIdx.x;
    __shared__ float us[HH];
    __shared__ float sc[SS];
    __shared__ float red[8];
    __shared__ float wsm[SS];
    const float* encb = enc + (size_t)b * SS * HH;
    us[t] = g_u[(size_t)b * HH + t];
    us[t + 256] = g_u[(size_t)b * HH + t + 256];
    __syncthreads();

    for (int s = 0; s < SS; s++) {
        float p = us[t] * encb[s * HH + t] + us[t + 256] * encb[s * HH + t + 256];
#pragma unroll
        for (int o = 16; o > 0; o >>= 1) p += __shfl_down_sync(0xffffffffu, p, o);
        if ((t & 31) == 0) red[t >> 5] = p;
        __syncthreads();
        if (t == 0) {
            float v = 0.f;
#pragma unroll
            for (int w = 0; w < 8; w++) v += red[w];
            sc[s] = v;
        }
        __syncthreads();
    }
    if (t == 0) {
        float m = -1e30f;
        for (int s = 0; s < SS; s++) m = fmaxf(m, sc[s]);
        float sum = 0.f;
        for (int s = 0; s < SS; s++) { float e = expf(sc[s] - m); wsm[s] = e; sum += e; }
        float inv = 1.f / sum;
        for (int s = 0; s < SS; s++) wsm[s] *= inv;
    }
    __syncthreads();
    if (t < SS) attn_out[(size_t)b * SS + t] = wsm[t];

    int tk = tok[b];
    const float* embrow = emb + (size_t)tk * HH;
    for (int h0 = t; h0 < HH; h0 += 256) {
        float ctx = 0.f;
#pragma unroll
        for (int s = 0; s < SS; s++) ctx = fmaf(wsm[s], encb[s * HH + h0], ctx);
        g_x[(size_t)b * 2 * HH + h0] = embrow[h0];
        g_x[(size_t)b * 2 * HH + HH + h0] = ctx;
    }
}

// ---------------------------------------------------------------------------
// C[M,N] = A[M,K] @ B[N,K]^T + bias[N]   (tf32 tensor cores, fp32 accumulate)
// Tile: BM=64, BN=128, BK=32. 256 threads, 8 warps (2x4), warp tile 32x32.
// M must be a multiple of 64; K a multiple of 32; N guarded.
// ---------------------------------------------------------------------------
__global__ void __launch_bounds__(256) gemm_tf32(const float* __restrict__ A,
                                                 const float* __restrict__ Bm,
                                                 const float* __restrict__ bias,
                                                 float* __restrict__ C,
                                                 int M, int N, int K) {
    __shared__ float As[64][36];   // stride 36 -> conflict-free frag reads
    __shared__ float Bs[128][36];
    int tid = threadIdx.x;
    int lane = tid & 31, warp = tid >> 5;
    int wm = warp >> 2, wn = warp & 3;
    int bm = blockIdx.x * 64, bn = blockIdx.y * 128;
    int gr = lane >> 2, tg = lane & 3;

    float acc[2][4][4];
#pragma unroll
    for (int i = 0; i < 2; i++)
#pragma unroll
        for (int j = 0; j < 4; j++)
#pragma unroll
            for (int q = 0; q < 4; q++) acc[i][j][q] = 0.f;

    for (int k0 = 0; k0 < K; k0 += 32) {
        // Stage A tile (64x32): 512 float4, 2 per thread
#pragma unroll
        for (int it = 0; it < 2; it++) {
            int f = tid + it * 256;
            int r = f >> 3, c4 = (f & 7) * 4;
            float4 v = *(const float4*)(A + (size_t)(bm + r) * K + k0 + c4);
            As[r][c4 + 0] = to_tf32(v.x);
            As[r][c4 + 1] = to_tf32(v.y);
            As[r][c4 + 2] = to_tf32(v.z);
            As[r][c4 + 3] = to_tf32(v.w);
        }
        // Stage B tile (128x32): 1024 float4, 4 per thread; guard N edge
#pragma unroll
        for (int it = 0; it < 4; it++) {
            int f = tid + it * 256;
            int r = f >> 3, c4 = (f & 7) * 4;
            int gn = bn + r;
            float4 v = make_float4(0.f, 0.f, 0.f, 0.f);
            if (gn < N) v = *(const float4*)(Bm + (size_t)gn * K + k0 + c4);
            Bs[r][c4 + 0] = to_tf32(v.x);
            Bs[r][c4 + 1] = to_tf32(v.y);
            Bs[r][c4 + 2] = to_tf32(v.z);
            Bs[r][c4 + 3] = to_tf32(v.w);
        }
        __syncthreads();

#pragma unroll
        for (int kk = 0; kk < 32; kk += 8) {
            uint32_t a[2][4], b[4][2];
#pragma unroll
            for (int i = 0; i < 2; i++) {
                int r0 = wm * 32 + i * 16 + gr;
                a[i][0] = __float_as_uint(As[r0][kk + tg]);
                a[i][1] = __float_as_uint(As[r0 + 8][kk + tg]);
                a[i][2] = __float_as_uint(As[r0][kk + tg + 4]);
                a[i][3] = __float_as_uint(As[r0 + 8][kk + tg + 4]);
            }
#pragma unroll
            for (int j = 0; j < 4; j++) {
                int c0 = wn * 32 + j * 8 + gr;
                b[j][0] = __float_as_uint(Bs[c0][kk + tg]);
                b[j][1] = __float_as_uint(Bs[c0][kk + tg + 4]);
            }
#pragma unroll
            for (int i = 0; i < 2; i++)
#pragma unroll
                for (int j = 0; j < 4; j++) mma_tf32(acc[i][j], a[i], b[j]);
        }
        __syncthreads();
    }

    // Epilogue: C = acc + bias
#pragma unroll
    for (int i = 0; i < 2; i++) {
#pragma unroll
        for (int j = 0; j < 4; j++) {
            int row = bm + wm * 32 + i * 16 + gr;
            int col = bn + wn * 32 + j * 8 + tg * 2;
            if (col < N) {
                float bv = bias[col];
                C[(size_t)row * N + col] = acc[i][j][0] + bv;
                C[(size_t)(row + 8) * N + col] = acc[i][j][2] + bv;
            }
            if (col + 1 < N) {
                float bv = bias[col + 1];
                C[(size_t)row * N + col + 1] = acc[i][j][1] + bv;
                C[(size_t)(row + 8) * N + col + 1] = acc[i][j][3] + bv;
            }
        }
    }
}

// ---------------------------------------------------------------------------
// GRU gates: h_new = (1-z)*n + z*h ; writes scratch + output hidden region
// ---------------------------------------------------------------------------
__global__ void __launch_bounds__(256) gate_kernel(const float* __restrict__ hprev,
                                                   float* __restrict__ out_h) {
    int idx = blockIdx.x * 256 + threadIdx.x;  // 0 .. B*H-1
    int b = idx >> 9, j = idx & 511;
    size_t gi0 = (size_t)b * 3 * HH + j;
    float i_r = g_gi[gi0], i_z = g_gi[gi0 + HH], i_n = g_gi[gi0 + 2 * HH];
    float h_r = g_gh[gi0], h_z = g_gh[gi0 + HH], h_n = g_gh[gi0 + 2 * HH];
    float r = 1.f / (1.f + expf(-(i_r + h_r)));
    float z = 1.f / (1.f + expf(-(i_z + h_z)));
    float n = tanhf(i_n + r * h_n);
    float h = hprev[idx];
    float hn = (1.f - z) * n + z * h;
    g_hnew[idx] = hn;
    out_h[idx] = hn;
}

// ---------------------------------------------------------------------------
// Per-row logsumexp over V (online, single pass)
// ---------------------------------------------------------------------------
__global__ void __launch_bounds__(256) lse_kernel(const float* __restrict__ logits) {
    int b = blockIdx.x, t = threadIdx.x;
    int lane = t & 31, warp = t >> 5;
    __shared__ float sm_m[8], sm_s[8];
    const float* row = logits + (size_t)b * VV;
    float m = -1e30f, s = 0.f;
    for (int i = t; i < VV; i += 256) {
        float v = row[i];
        float nm = fmaxf(m, v);
        s = s * __expf(m - nm) + __expf(v - nm);
        m = nm;
    }
#pragma unroll
    for (int o = 16; o > 0; o >>= 1) {
        float om = __shfl_down_sync(0xffffffffu, m, o);
        float os = __shfl_down_sync(0xffffffffu, s, o);
        float nm = fmaxf(m, om);
        s = s * __expf(m - nm) + os * __expf(om - nm);
        m = nm;
    }
    if (lane == 0) { sm_m[warp] = m; sm_s[warp] = s; }
    __syncthreads();
    if (t == 0) {
        float M = sm_m[0], Ssum = sm_s[0];
#pragma unroll
        for (int w = 1; w < 8; w++) {
            float nm = fmaxf(M, sm_m[w]);
            Ssum = Ssum * __expf(M - nm) + sm_s[w] * __expf(sm_m[w] - nm);
            M = nm;
        }
        g_lse[b] = M + logf(Ssum);
    }
}

// log_probs = logits - lse[b]; grid (ceil(V/256), B)
__global__ void __launch_bounds__(256) sub_kernel(float* __restrict__ lg) {
    int b = blockIdx.y;
    int c = blockIdx.x * 256 + threadIdx.x;
    if (c < VV) lg[(size_t)b * VV + c] -= g_lse[b];
}

// ---------------------------------------------------------------------------
extern "C" void kernel_launch(void* const* d_in, const int* in_sizes, int n_in,
                              void* d_out, int out_size) {
    (void)in_sizes; (void)n_in; (void)out_size;
    const int*   tok    = (const int*)d_in[0];
    const float* hidden = (const float*)d_in[1];
    const float* enc    = (const float*)d_in[2];
    const float* emb    = (const float*)d_in[3];
    const float* attnW  = (const float*)d_in[4];
    // d_in[5] = attn_b: provably unused (per-batch constant cancels in softmax)
    const float* W_ih   = (const float*)d_in[6];
    const float* W_hh   = (const float*)d_in[7];
    const float* b_ih   = (const float*)d_in[8];
    const float* b_hh   = (const float*)d_in[9];
    const float* out_W  = (const float*)d_in[10];
    const float* out_b  = (const float*)d_in[11];

    float* out        = (float*)d_out;
    float* out_logits = out;                              // [B, V]
    float* out_h      = out + (size_t)BB * VV;            // [1, B, H]
    float* out_attn   = out_h + (size_t)BB * HH;          // [B, S]

    float *p_x, *p_gi, *p_gh, *p_hnew;
    cudaGetSymbolAddress((void**)&p_x, g_x);
    cudaGetSymbolAddress((void**)&p_gi, g_gi);
    cudaGetSymbolAddress((void**)&p_gh, g_gh);
    cudaGetSymbolAddress((void**)&p_hnew, g_hnew);

    // 1) u = h @ attn_W (fp32)
    u_kernel<<<dim3(16, 4), 128>>>(hidden, attnW);
    // 2) scores/softmax/context -> attn_weights out, x scratch
    attn_kernel<<<BB, 256>>>(enc, tok, emb, out_attn);
    // 3) GRU input & hidden GEMMs (tf32 TC)
    gemm_tf32<<<dim3(4, 12), 256>>>(p_x, W_ih, b_ih, p_gi, BB, 3 * HH, 2 * HH);
    gemm_tf32<<<dim3(4, 12), 256>>>(hidden, W_hh, b_hh, p_gh, BB, 3 * HH, HH);
    // 4) gates -> h_new (scratch + output)
    gate_kernel<<<(BB * HH) / 256, 256>>>(hidden, out_h);
    // 5) logits = h_new @ out_W^T + out_b (tf32 TC)
    gemm_tf32<<<dim3(4, (VV + 127) / 128), 256>>>(p_hnew, out_W, out_b, out_logits,
                                                  BB, VV, HH);
    // 6) log_softmax
    lse_kernel<<<BB, 256>>>(out_logits);
    sub_kernel<<<dim3((VV + 255) / 256, BB), 256>>>(out_logits);
}

// round 3
// speedup vs baseline: 1.4259x; 1.4259x over previous
#include <cuda_runtime.h>
#include <cuda_bf16.h>
#include <math.h>
#include <stdint.h>

#define BB 256
#define SS 15
#define HH 512
#define VV 50257

// Scratch (device globals: no allocation allowed)
__device__ float g_u[BB * HH];
__device__ float g_x[BB * 2 * HH];
__device__ float g_gi[BB * 3 * HH];
__device__ float g_gh[BB * 3 * HH];
__device__ float g_hnew[BB * HH];
__device__ float g_lse[BB];

__device__ __forceinline__ float to_tf32(float x) {
    float y;
    asm("cvt.rna.tf32.f32 %0, %1;" : "=f"(y) : "f"(x));
    return y;
}
__device__ __forceinline__ uint32_t ldtf(const float* p) {
    return __float_as_uint(to_tf32(*p));
}

__device__ __forceinline__ void mma_tf32(float* d, const uint32_t* a, const uint32_t* b) {
    asm volatile(
        "mma.sync.aligned.m16n8k8.row.col.f32.tf32.tf32.f32 "
        "{%0,%1,%2,%3},{%4,%5,%6,%7},{%8,%9},{%0,%1,%2,%3};\n"
        : "+f"(d[0]), "+f"(d[1]), "+f"(d[2]), "+f"(d[3])
        : "r"(a[0]), "r"(a[1]), "r"(a[2]), "r"(a[3]), "r"(b[0]), "r"(b[1]));
}

__device__ __forceinline__ void cp16(uint32_t dst, const void* src) {
    asm volatile("cp.async.cg.shared.global [%0], [%1], 16;\n" ::"r"(dst), "l"(src));
}
__device__ __forceinline__ void cp16z(uint32_t dst, const void* src, bool valid) {
    int sz = valid ? 16 : 0;
    asm volatile("cp.async.cg.shared.global [%0], [%1], 16, %2;\n" ::"r"(dst), "l"(src), "r"(sz));
}
#define CP_COMMIT asm volatile("cp.async.commit_group;\n")
#define CP_WAIT1 asm volatile("cp.async.wait_group 1;\n")
#define CP_WAIT0 asm volatile("cp.async.wait_group 0;\n")

// ---------------------------------------------------------------------------
// u[b,j] = sum_o h[b,o] * attn_W[o,j]   (fp32; attention path stays exact)
// ---------------------------------------------------------------------------
__global__ void __launch_bounds__(128) u_kernel(const float* __restrict__ h,
                                                const float* __restrict__ W) {
    __shared__ float hs[16][HH];
    int mb = blockIdx.x * 16;
    int j = blockIdx.y * 128 + threadIdx.x;
    for (int i = threadIdx.x; i < 16 * HH; i += 128)
        hs[i / HH][i % HH] = h[(size_t)(mb + i / HH) * HH + (i % HH)];
    __syncthreads();
    float acc[16];
#pragma unroll
    for (int m = 0; m < 16; m++) acc[m] = 0.f;
    for (int o = 0; o < HH; o++) {
        float w = W[(size_t)o * HH + j];
#pragma unroll
        for (int m = 0; m < 16; m++) acc[m] = fmaf(hs[m][o], w, acc[m]);
    }
#pragma unroll
    for (int m = 0; m < 16; m++) g_u[(size_t)(mb + m) * HH + j] = acc[m];
}

// ---------------------------------------------------------------------------
// Per-batch: scores -> softmax -> context; writes attn_weights + x scratch.
// (h . attn_b) is a per-batch constant -> cancels in softmax -> attn_b unused.
// ---------------------------------------------------------------------------
__global__ void __launch_bounds__(256) attn_kernel(const float* __restrict__ enc,
                                                   const int* __restrict__ tok,
                                                   const float* __restrict__ emb,
                                                   float* __restrict__ attn_out) {
    int b = blockIdx.x;
    int t = threadIdx.x;
    __shared__ float us[HH];
    __shared__ float sc[SS];
    __shared__ float red[8];
    __shared__ float wsm[SS];
    const float* encb = enc + (size_t)b * SS * HH;
    us[t] = g_u[(size_t)b * HH + t];
    us[t + 256] = g_u[(size_t)b * HH + t + 256];
    __syncthreads();

    for (int s = 0; s < SS; s++) {
        float p = us[t] * encb[s * HH + t] + us[t + 256] * encb[s * HH + t + 256];
#pragma unroll
        for (int o = 16; o > 0; o >>= 1) p += __shfl_down_sync(0xffffffffu, p, o);
        if ((t & 31) == 0) red[t >> 5] = p;
        __syncthreads();
        if (t == 0) {
            float v = 0.f;
#pragma unroll
            for (int w = 0; w < 8; w++) v += red[w];
            sc[s] = v;
        }
        __syncthreads();
    }
    if (t == 0) {
        float m = -1e30f;
        for (int s = 0; s < SS; s++) m = fmaxf(m, sc[s]);
        float sum = 0.f;
        for (int s = 0; s < SS; s++) { float e = expf(sc[s] - m); wsm[s] = e; sum += e; }
        float inv = 1.f / sum;
        for (int s = 0; s < SS; s++) wsm[s] *= inv;
    }
    __syncthreads();
    if (t < SS) attn_out[(size_t)b * SS + t] = wsm[t];

    int tk = tok[b];
    const float* embrow = emb + (size_t)tk * HH;
    for (int h0 = t; h0 < HH; h0 += 256) {
        float ctx = 0.f;
#pragma unroll
        for (int s = 0; s < SS; s++) ctx = fmaf(wsm[s], encb[s * HH + h0], ctx);
        g_x[(size_t)b * 2 * HH + h0] = embrow[h0];
        g_x[(size_t)b * 2 * HH + HH + h0] = ctx;
    }
}

// ---------------------------------------------------------------------------
// Logits GEMM: C[256, V] = A[256,512] @ B[V,512]^T + bias, tf32 TC,
// cp.async double-buffered. BM=128 BN=128 BK=32, 256 thr, 8 warps (2x4).
// ---------------------------------------------------------------------------
#define LST 36  // padded smem row stride (floats); 144B = 9 x 16B (cp.async ok)

__global__ void __launch_bounds__(256, 2) gemm_logits(const float* __restrict__ A,
                                                      const float* __restrict__ Bm,
                                                      const float* __restrict__ bias,
                                                      float* __restrict__ C) {
    extern __shared__ float smem[];
    float* As = smem;                  // [2][128][LST]
    float* Bs = smem + 2 * 128 * LST;  // [2][128][LST]
    const int N = VV, K = HH;
    int tid = threadIdx.x, lane = tid & 31, warp = tid >> 5;
    int wm = warp >> 2, wn = warp & 3;
    int gr = lane >> 2, tg = lane & 3;
    int bm = blockIdx.x * 128, bn = blockIdx.y * 128;

    uint32_t asB = (uint32_t)__cvta_generic_to_shared(As);
    uint32_t bsB = (uint32_t)__cvta_generic_to_shared(Bs);

    float acc[4][4][4];
#pragma unroll
    for (int i = 0; i < 4; i++)
#pragma unroll
        for (int j = 0; j < 4; j++)
#pragma unroll
            for (int q = 0; q < 4; q++) acc[i][j][q] = 0.f;

    auto load_tile = [&](int kt, int s) {
        int k0 = kt * 32;
#pragma unroll
        for (int it = 0; it < 4; it++) {
            int id = tid + it * 256;
            int r = id >> 3, c = id & 7;
            cp16(asB + (((s * 128 + r) * LST) + c * 4) * 4,
                 A + (size_t)(bm + r) * K + k0 + c * 4);
        }
#pragma unroll
        for (int it = 0; it < 4; it++) {
            int id = tid + it * 256;
            int r = id >> 3, c = id & 7;
            int gn = bn + r;
            int gc = gn < N ? gn : N - 1;
            cp16z(bsB + (((s * 128 + r) * LST) + c * 4) * 4,
                  Bm + (size_t)gc * K + k0 + c * 4, gn < N);
        }
        CP_COMMIT;
    };

    const int NT = K / 32;  // 16
    load_tile(0, 0);
    for (int kt = 0; kt < NT; kt++) {
        if (kt + 1 < NT) { load_tile(kt + 1, (kt + 1) & 1); CP_WAIT1; }
        else { CP_WAIT0; }
        __syncthreads();
        int s = kt & 1;
#pragma unroll
        for (int kk = 0; kk < 32; kk += 8) {
            uint32_t a[4][4], b[4][2];
#pragma unroll
            for (int i = 0; i < 4; i++) {
                const float* r0 = As + (s * 128 + wm * 64 + i * 16 + gr) * LST + kk;
                a[i][0] = ldtf(r0 + tg);
                a[i][1] = ldtf(r0 + 8 * LST + tg);
                a[i][2] = ldtf(r0 + tg + 4);
                a[i][3] = ldtf(r0 + 8 * LST + tg + 4);
            }
#pragma unroll
            for (int j = 0; j < 4; j++) {
                const float* c0 = Bs + (s * 128 + wn * 32 + j * 8 + gr) * LST + kk;
                b[j][0] = ldtf(c0 + tg);
                b[j][1] = ldtf(c0 + tg + 4);
            }
#pragma unroll
            for (int i = 0; i < 4; i++)
#pragma unroll
                for (int j = 0; j < 4; j++) mma_tf32(acc[i][j], a[i], b[j]);
        }
        __syncthreads();
    }

#pragma unroll
    for (int i = 0; i < 4; i++) {
#pragma unroll
        for (int j = 0; j < 4; j++) {
            int row = bm + wm * 64 + i * 16 + gr;
            int col = bn + wn * 32 + j * 8 + tg * 2;
            if (col < N) {
                float bv = bias[col];
                C[(size_t)row * N + col] = acc[i][j][0] + bv;
                C[(size_t)(row + 8) * N + col] = acc[i][j][2] + bv;
            }
            if (col + 1 < N) {
                float bv = bias[col + 1];
                C[(size_t)row * N + col + 1] = acc[i][j][1] + bv;
                C[(size_t)(row + 8) * N + col + 1] = acc[i][j][3] + bv;
            }
        }
    }
}

// ---------------------------------------------------------------------------
// Fused GRU GEMM: accumulate x@W_ih^T over k<1024 then h@W_hh^T over k<512,
// snapshot accumulators at the boundary so gi/gh stay separate (r*h_n term).
// BM=64 BN=64 BK=32, 128 thr, 4 warps (2x2), grid (4, 24) = 96 blocks.
// ---------------------------------------------------------------------------
__global__ void __launch_bounds__(128) gemm_gru(const float* __restrict__ Xp,
                                                const float* __restrict__ Hp,
                                                const float* __restrict__ Wih,
                                                const float* __restrict__ Whh,
                                                const float* __restrict__ bih,
                                                const float* __restrict__ bhh) {
    __shared__ float As[2][64][LST];
    __shared__ float Bs[2][64][LST];
    int tid = threadIdx.x, lane = tid & 31, warp = tid >> 5;
    int wm = warp >> 1, wn = warp & 1;
    int gr = lane >> 2, tg = lane & 3;
    int bm = blockIdx.x * 64, bn = blockIdx.y * 64;

    uint32_t asB = (uint32_t)__cvta_generic_to_shared(&As[0][0][0]);
    uint32_t bsB = (uint32_t)__cvta_generic_to_shared(&Bs[0][0][0]);

    float acc[2][4][4], snap[2][4][4];
#pragma unroll
    for (int i = 0; i < 2; i++)
#pragma unroll
        for (int j = 0; j < 4; j++)
#pragma unroll
            for (int q = 0; q < 4; q++) acc[i][j][q] = 0.f;

    auto load_tile = [&](int kt, int s) {
        int k0 = kt * 32;
        const float *Ap, *Bp;
        int la, lb, kl;
        if (k0 < 2 * HH) { Ap = Xp; la = 2 * HH; Bp = Wih; lb = 2 * HH; kl = k0; }
        else { Ap = Hp; la = HH; Bp = Whh; lb = HH; kl = k0 - 2 * HH; }
#pragma unroll
        for (int it = 0; it < 4; it++) {
            int id = tid + it * 128;
            int r = id >> 3, c = id & 7;
            cp16(asB + (((s * 64 + r) * LST) + c * 4) * 4,
                 Ap + (size_t)(bm + r) * la + kl + c * 4);
        }
#pragma unroll
        for (int it = 0; it < 4; it++) {
            int id = tid + it * 128;
            int r = id >> 3, c = id & 7;
            cp16(bsB + (((s * 64 + r) * LST) + c * 4) * 4,
                 Bp + (size_t)(bn + r) * lb + kl + c * 4);
        }
        CP_COMMIT;
    };

    const int NT = 48;   // (1024 + 512) / 32
    const int KT1 = 32;  // boundary tile index
    load_tile(0, 0);
    for (int kt = 0; kt < NT; kt++) {
        if (kt + 1 < NT) { load_tile(kt + 1, (kt + 1) & 1); CP_WAIT1; }
        else { CP_WAIT0; }
        __syncthreads();
        int s = kt & 1;
#pragma unroll
        for (int kk = 0; kk < 32; kk += 8) {
            uint32_t a[2][4], b[4][2];
#pragma unroll
            for (int i = 0; i < 2; i++) {
                const float* r0 = &As[s][wm * 32 + i * 16 + gr][kk];
                a[i][0] = ldtf(r0 + tg);
                a[i][1] = ldtf(r0 + 8 * LST + tg);
                a[i][2] = ldtf(r0 + tg + 4);
                a[i][3] = ldtf(r0 + 8 * LST + tg + 4);
            }
#pragma unroll
            for (int j = 0; j < 4; j++) {
                const float* c0 = &Bs[s][wn * 32 + j * 8 + gr][kk];
                b[j][0] = ldtf(c0 + tg);
                b[j][1] = ldtf(c0 + tg + 4);
            }
#pragma unroll
            for (int i = 0; i < 2; i++)
#pragma unroll
                for (int j = 0; j < 4; j++) mma_tf32(acc[i][j], a[i], b[j]);
        }
        if (kt == KT1 - 1) {  // snapshot gi partial sums
#pragma unroll
            for (int i = 0; i < 2; i++)
#pragma unroll
                for (int j = 0; j < 4; j++)
#pragma unroll
                    for (int q = 0; q < 4; q++) snap[i][j][q] = acc[i][j][q];
        }
        __syncthreads();
    }

    const int N = 3 * HH;
#pragma unroll
    for (int i = 0; i < 2; i++) {
#pragma unroll
        for (int j = 0; j < 4; j++) {
            int row = bm + wm * 32 + i * 16 + gr;
            int col = bn + wn * 32 + j * 8 + tg * 2;
#pragma unroll
            for (int q = 0; q < 2; q++) {
                int cc = col + q;
                float gi0 = snap[i][j][q] + bih[cc];
                float gh0 = (acc[i][j][q] - snap[i][j][q]) + bhh[cc];
                float gi1 = snap[i][j][q + 2] + bih[cc];
                float gh1 = (acc[i][j][q + 2] - snap[i][j][q + 2]) + bhh[cc];
                g_gi[(size_t)row * N + cc] = gi0;
                g_gh[(size_t)row * N + cc] = gh0;
                g_gi[(size_t)(row + 8) * N + cc] = gi1;
                g_gh[(size_t)(row + 8) * N + cc] = gh1;
            }
        }
    }
}

// ---------------------------------------------------------------------------
__global__ void __launch_bounds__(256) gate_kernel(const float* __restrict__ hprev,
                                                   float* __restrict__ out_h) {
    int idx = blockIdx.x * 256 + threadIdx.x;
    int b = idx >> 9, j = idx & 511;
    size_t gi0 = (size_t)b * 3 * HH + j;
    float i_r = g_gi[gi0], i_z = g_gi[gi0 + HH], i_n = g_gi[gi0 + 2 * HH];
    float h_r = g_gh[gi0], h_z = g_gh[gi0 + HH], h_n = g_gh[gi0 + 2 * HH];
    float r = 1.f / (1.f + expf(-(i_r + h_r)));
    float z = 1.f / (1.f + expf(-(i_z + h_z)));
    float n = tanhf(i_n + r * h_n);
    float h = hprev[idx];
    float hn = (1.f - z) * n + z * h;
    g_hnew[idx] = hn;
    out_h[idx] = hn;
}

// ---------------------------------------------------------------------------
__global__ void __launch_bounds__(256) lse_kernel(const float* __restrict__ logits) {
    int b = blockIdx.x, t = threadIdx.x;
    int lane = t & 31, warp = t >> 5;
    __shared__ float sm_m[8], sm_s[8];
    const float* row = logits + (size_t)b * VV;
    float m = -1e30f, s = 0.f;
    for (int i = t; i < VV; i += 256) {
        float v = row[i];
        float nm = fmaxf(m, v);
        s = s * __expf(m - nm) + __expf(v - nm);
        m = nm;
    }
#pragma unroll
    for (int o = 16; o > 0; o >>= 1) {
        float om = __shfl_down_sync(0xffffffffu, m, o);
        float os = __shfl_down_sync(0xffffffffu, s, o);
        float nm = fmaxf(m, om);
        s = s * __expf(m - nm) + os * __expf(om - nm);
        m = nm;
    }
    if (lane == 0) { sm_m[warp] = m; sm_s[warp] = s; }
    __syncthreads();
    if (t == 0) {
        float M = sm_m[0], Ssum = sm_s[0];
#pragma unroll
        for (int w = 1; w < 8; w++) {
            float nm = fmaxf(M, sm_m[w]);
            Ssum = Ssum * __expf(M - nm) + sm_s[w] * __expf(sm_m[w] - nm);
            M = nm;
        }
        g_lse[b] = M + logf(Ssum);
    }
}

__global__ void __launch_bounds__(256) sub_kernel(float* __restrict__ lg) {
    int b = blockIdx.y;
    int c = blockIdx.x * 256 + threadIdx.x;
    if (c < VV) lg[(size_t)b * VV + c] -= g_lse[b];
}

// ---------------------------------------------------------------------------
extern "C" void kernel_launch(void* const* d_in, const int* in_sizes, int n_in,
                              void* d_out, int out_size) {
    (void)in_sizes; (void)n_in; (void)out_size;
    const int*   tok    = (const int*)d_in[0];
    const float* hidden = (const float*)d_in[1];
    const float* enc    = (const float*)d_in[2];
    const float* emb    = (const float*)d_in[3];
    const float* attnW  = (const float*)d_in[4];
    // d_in[5] = attn_b: unused (cancels in softmax)
    const float* W_ih   = (const float*)d_in[6];
    const float* W_hh   = (const float*)d_in[7];
    const float* b_ih   = (const float*)d_in[8];
    const float* b_hh   = (const float*)d_in[9];
    const float* out_W  = (const float*)d_in[10];
    const float* out_b  = (const float*)d_in[11];

    float* out        = (float*)d_out;
    float* out_logits = out;
    float* out_h      = out + (size_t)BB * VV;
    float* out_attn   = out_h + (size_t)BB * HH;

    float *p_x, *p_hnew;
    cudaGetSymbolAddress((void**)&p_x, g_x);
    cudaGetSymbolAddress((void**)&p_hnew, g_hnew);

    static bool attr_set = false;
    if (!attr_set) {
        cudaFuncSetAttribute(gemm_logits, cudaFuncAttributeMaxDynamicSharedMemorySize,
                             2 * 2 * 128 * LST * 4);
        attr_set = true;
    }

    // 1) u = h @ attn_W (fp32)
    u_kernel<<<dim3(16, 4), 128>>>(hidden, attnW);
    // 2) softmax attention -> attn_weights + x
    attn_kernel<<<BB, 256>>>(enc, tok, emb, out_attn);
    // 3) fused GRU gate GEMM (pipelined tf32)
    gemm_gru<<<dim3(4, 24), 128>>>(p_x, hidden, W_ih, W_hh, b_ih, b_hh);
    // 4) gates -> h_new
    gate_kernel<<<(BB * HH) / 256, 256>>>(hidden, out_h);
    // 5) logits (pipelined tf32)
    gemm_logits<<<dim3(2, (VV + 127) / 128), 256, 2 * 2 * 128 * LST * 4>>>(
        p_hnew, out_W, out_b, out_logits);
    // 6) log_softmax
    lse_kernel<<<BB, 256>>>(out_logits);
    sub_kernel<<<dim3((VV + 255) / 256, BB), 256>>>(out_logits);
}

// round 6
// speedup vs baseline: 1.5562x; 1.0914x over previous
#include <cuda_runtime.h>
#include <cuda_fp16.h>
#include <math.h>
#include <stdint.h>

#define BB 256
#define SS 15
#define HH 512
#define VV 50257

// Scratch (device globals: no allocation allowed)
__device__ float g_u[BB * HH];
__device__ float g_x[BB * 2 * HH];
__device__ float g_gi[BB * 3 * HH];
__device__ float g_gh[BB * 3 * HH];
__device__ __align__(128) __half g_hnewh[BB * HH];
__device__ __align__(128) __half g_wh[(size_t)VV * HH];  // fp16 copy of out_W

// ---------------------------------------------------------------------------
// helpers
// ---------------------------------------------------------------------------
__device__ __forceinline__ float to_tf32(float x) {
    float y;
    asm("cvt.rna.tf32.f32 %0, %1;" : "=f"(y) : "f"(x));
    return y;
}
__device__ __forceinline__ uint32_t ldtf(const float* p) {
    return __float_as_uint(to_tf32(*p));
}
__device__ __forceinline__ void mma_sync_tf32(float* d, const uint32_t* a, const uint32_t* b) {
    asm volatile(
        "mma.sync.aligned.m16n8k8.row.col.f32.tf32.tf32.f32 "
        "{%0,%1,%2,%3},{%4,%5,%6,%7},{%8,%9},{%0,%1,%2,%3};\n"
        : "+f"(d[0]), "+f"(d[1]), "+f"(d[2]), "+f"(d[3])
        : "r"(a[0]), "r"(a[1]), "r"(a[2]), "r"(a[3]), "r"(b[0]), "r"(b[1]));
}
__device__ __forceinline__ void mma_sync_f16(float* d, const uint32_t* a, const uint32_t* b) {
    asm volatile(
        "mma.sync.aligned.m16n8k16.row.col.f32.f16.f16.f32 "
        "{%0,%1,%2,%3},{%4,%5,%6,%7},{%8,%9},{%0,%1,%2,%3};\n"
        : "+f"(d[0]), "+f"(d[1]), "+f"(d[2]), "+f"(d[3])
        : "r"(a[0]), "r"(a[1]), "r"(a[2]), "r"(a[3]), "r"(b[0]), "r"(b[1]));
}
__device__ __forceinline__ void ldmatrix_x4(uint32_t* r, uint32_t addr) {
    asm volatile(
        "ldmatrix.sync.aligned.m8n8.x4.shared.b16 {%0,%1,%2,%3}, [%4];"
        : "=r"(r[0]), "=r"(r[1]), "=r"(r[2]), "=r"(r[3])
        : "r"(addr));
}
__device__ __forceinline__ void cp16(uint32_t dst, const void* src) {
    asm volatile("cp.async.cg.shared.global [%0], [%1], 16;\n" ::"r"(dst), "l"(src));
}
#define CP_COMMIT asm volatile("cp.async.commit_group;\n")
#define CP_WAIT1 asm volatile("cp.async.wait_group 1;\n")
#define CP_WAIT0 asm volatile("cp.async.wait_group 0;\n")

// ---------------------------------------------------------------------------
// out_W fp32 -> fp16  (one pass; 16 elems per thread)
// ---------------------------------------------------------------------------
__global__ void __launch_bounds__(512) convw_kernel(const float* __restrict__ W) {
    size_t i = ((size_t)blockIdx.x * 512 + threadIdx.x) * 16;
    const size_t total = (size_t)VV * HH;
    if (i >= total) return;
    float4 v0 = *(const float4*)(W + i);
    float4 v1 = *(const float4*)(W + i + 4);
    float4 v2 = *(const float4*)(W + i + 8);
    float4 v3 = *(const float4*)(W + i + 12);
    __half h[16];
    h[0] = __float2half_rn(v0.x); h[1] = __float2half_rn(v0.y);
    h[2] = __float2half_rn(v0.z); h[3] = __float2half_rn(v0.w);
    h[4] = __float2half_rn(v1.x); h[5] = __float2half_rn(v1.y);
    h[6] = __float2half_rn(v1.z); h[7] = __float2half_rn(v1.w);
    h[8] = __float2half_rn(v2.x); h[9] = __float2half_rn(v2.y);
    h[10] = __float2half_rn(v2.z); h[11] = __float2half_rn(v2.w);
    h[12] = __float2half_rn(v3.x); h[13] = __float2half_rn(v3.y);
    h[14] = __float2half_rn(v3.z); h[15] = __float2half_rn(v3.w);
    *(uint4*)(g_wh + i) = *(const uint4*)h;
    *(uint4*)(g_wh + i + 8) = *(const uint4*)(h + 8);
}

// ---------------------------------------------------------------------------
// u[b,j] = sum_o h[b,o] * attn_W[o,j]   (fp32; attention path stays exact)
// ---------------------------------------------------------------------------
__global__ void __launch_bounds__(128) u_kernel(const float* __restrict__ h,
                                                const float* __restrict__ W) {
    __shared__ float hs[16][HH];
    int mb = blockIdx.x * 16;
    int j = blockIdx.y * 128 + threadIdx.x;
    for (int i = threadIdx.x; i < 16 * HH; i += 128)
        hs[i / HH][i % HH] = h[(size_t)(mb + i / HH) * HH + (i % HH)];
    __syncthreads();
    float acc[16];
#pragma unroll
    for (int m = 0; m < 16; m++) acc[m] = 0.f;
    for (int o = 0; o < HH; o++) {
        float w = W[(size_t)o * HH + j];
#pragma unroll
        for (int m = 0; m < 16; m++) acc[m] = fmaf(hs[m][o], w, acc[m]);
    }
#pragma unroll
    for (int m = 0; m < 16; m++) g_u[(size_t)(mb + m) * HH + j] = acc[m];
}

// ---------------------------------------------------------------------------
// Per-batch: scores -> softmax -> context; writes attn_weights + x scratch.
// (h . attn_b) is a per-batch constant -> cancels in softmax -> attn_b unused.
// ---------------------------------------------------------------------------
__global__ void __launch_bounds__(256) attn_kernel(const float* __restrict__ enc,
                                                   const int* __restrict__ tok,
                                                   const float* __restrict__ emb,
                                                   float* __restrict__ attn_out) {
    int b = blockIdx.x;
    int t = threadIdx.x;
    __shared__ float us[HH];
    __shared__ float sc[SS];
    __shared__ float red[8];
    __shared__ float wsm[SS];
    const float* encb = enc + (size_t)b * SS * HH;
    us[t] = g_u[(size_t)b * HH + t];
    us[t + 256] = g_u[(size_t)b * HH + t + 256];
    __syncthreads();

    for (int s = 0; s < SS; s++) {
        float p = us[t] * encb[s * HH + t] + us[t + 256] * encb[s * HH + t + 256];
#pragma unroll
        for (int o = 16; o > 0; o >>= 1) p += __shfl_down_sync(0xffffffffu, p, o);
        if ((t & 31) == 0) red[t >> 5] = p;
        __syncthreads();
        if (t == 0) {
            float v = 0.f;
#pragma unroll
            for (int w = 0; w < 8; w++) v += red[w];
            sc[s] = v;
        }
        __syncthreads();
    }
    if (t == 0) {
        float m = -1e30f;
        for (int s = 0; s < SS; s++) m = fmaxf(m, sc[s]);
        float sum = 0.f;
        for (int s = 0; s < SS; s++) { float e = expf(sc[s] - m); wsm[s] = e; sum += e; }
        float inv = 1.f / sum;
        for (int s = 0; s < SS; s++) wsm[s] *= inv;
    }
    __syncthreads();
    if (t < SS) attn_out[(size_t)b * SS + t] = wsm[t];

    int tk = tok[b];
    const float* embrow = emb + (size_t)tk * HH;
    for (int h0 = t; h0 < HH; h0 += 256) {
        float ctx = 0.f;
#pragma unroll
        for (int s = 0; s < SS; s++) ctx = fmaf(wsm[s], encb[s * HH + h0], ctx);
        g_x[(size_t)b * 2 * HH + h0] = embrow[h0];
        g_x[(size_t)b * 2 * HH + HH + h0] = ctx;
    }
}

// ---------------------------------------------------------------------------
// Logits GEMM (fp16 mma.sync m16n8k16): C[256,V] = A[256,512] @ B[V,512]^T + b
// BM=256 (out_W read once), BN=128, BK=32, 512 thr / 16 warps (4M x 4N),
// warp tile 64x32. cp.async double-buffered on pure fp16 tiles.
// smem halves layout, row stride 40 halves (80B, conflict-free ldmatrix/LDS).
//   A stage s at byte  s*20480          (256 rows)
//   B stage s at byte  40960 + s*10240  (128 rows)
// ---------------------------------------------------------------------------
__global__ void __launch_bounds__(512) gemm_logits_f16(const float* __restrict__ bias,
                                                       float* __restrict__ C) {
    extern __shared__ __half sm[];
    uint32_t base = (uint32_t)__cvta_generic_to_shared(sm);
    int tid = threadIdx.x;
    int lane = tid & 31, warp = tid >> 5;
    int wm = warp >> 2, wn = warp & 3;      // 4 x 4 warps
    int bn = blockIdx.x * 128;

    float acc[4][4][4];
#pragma unroll
    for (int i = 0; i < 4; i++)
#pragma unroll
        for (int j = 0; j < 4; j++)
#pragma unroll
            for (int q = 0; q < 4; q++) acc[i][j][q] = 0.f;

    auto load_blk = [&](int kt, int s) {
        int k0 = kt * 32;
        // A: 256 rows x 32 halves = 1024 x 16B chunks, 2 per thread
#pragma unroll
        for (int it = 0; it < 2; it++) {
            int id = tid + it * 512;
            int r = id >> 2, c = id & 3;
            cp16(base + (uint32_t)(s * 20480 + r * 80 + c * 16),
                 g_hnewh + (size_t)r * HH + k0 + c * 8);
        }
        // B: 128 rows x 32 halves = 512 chunks, 1 per thread
        {
            int r = tid >> 2, c = tid & 3;
            int gn = bn + r;
            int gc = gn < VV ? gn : VV - 1;
            cp16(base + (uint32_t)(40960 + s * 10240 + r * 80 + c * 16),
                 g_wh + (size_t)gc * HH + k0 + c * 8);
        }
        CP_COMMIT;
    };

    const int NT = HH / 32;  // 16
    load_blk(0, 0);
    load_blk(1, 1);
    for (int kt = 0; kt < NT; kt++) {
        int s = kt & 1;
        if (kt == NT - 1) { CP_WAIT0; } else { CP_WAIT1; }
        __syncthreads();
        uint32_t aBase = base + (uint32_t)(s * 20480);
        uint32_t bBase = base + (uint32_t)(40960 + s * 10240);
#pragma unroll
        for (int kk = 0; kk < 32; kk += 16) {
            uint32_t a[4][4], b[4][2];
#pragma unroll
            for (int mi = 0; mi < 4; mi++) {
                int row = wm * 64 + mi * 16 + (lane & 15);
                uint32_t addr = aBase + (uint32_t)(row * 80 + (kk + ((lane >> 4) << 3)) * 2);
                ldmatrix_x4(a[mi], addr);
            }
#pragma unroll
            for (int nj = 0; nj < 4; nj++) {
                int row = wn * 32 + nj * 8 + (lane >> 2);
                const __half* p = sm + (size_t)0;  // silence unused
                (void)p;
                uint32_t off = (uint32_t)(row * 80 + (kk + (lane & 3) * 2) * 2);
                asm volatile("ld.shared.b32 %0, [%1];" : "=r"(b[nj][0]) : "r"(bBase + off));
                asm volatile("ld.shared.b32 %0, [%1];" : "=r"(b[nj][1]) : "r"(bBase + off + 16));
            }
#pragma unroll
            for (int mi = 0; mi < 4; mi++)
#pragma unroll
                for (int nj = 0; nj < 4; nj++) mma_sync_f16(acc[mi][nj], a[mi], b[nj]);
        }
        __syncthreads();
        if (kt + 2 < NT) load_blk(kt + 2, s);
    }

    // Epilogue: direct stores + bias
#pragma unroll
    for (int mi = 0; mi < 4; mi++) {
        int row = wm * 64 + mi * 16 + (lane >> 2);
#pragma unroll
        for (int nj = 0; nj < 4; nj++) {
            int col = bn + wn * 32 + nj * 8 + (lane & 3) * 2;
            if (col < VV) {
                float bv = bias[col];
                C[(size_t)row * VV + col] = acc[mi][nj][0] + bv;
                C[(size_t)(row + 8) * VV + col] = acc[mi][nj][2] + bv;
            }
            if (col + 1 < VV) {
                float bv = bias[col + 1];
                C[(size_t)row * VV + col + 1] = acc[mi][nj][1] + bv;
                C[(size_t)(row + 8) * VV + col + 1] = acc[mi][nj][3] + bv;
            }
        }
    }
}

// ---------------------------------------------------------------------------
// Fused GRU GEMM (mma.sync tf32, pipelined) — unchanged (known good)
// ---------------------------------------------------------------------------
#define LST 36

__global__ void __launch_bounds__(128) gemm_gru(const float* __restrict__ Xp,
                                                const float* __restrict__ Hp,
                                                const float* __restrict__ Wih,
                                                const float* __restrict__ Whh,
                                                const float* __restrict__ bih,
                                                const float* __restrict__ bhh) {
    __shared__ float As[2][64][LST];
    __shared__ float Bs[2][64][LST];
    int tid = threadIdx.x, lane = tid & 31, warp = tid >> 5;
    int wm = warp >> 1, wn = warp & 1;
    int gr = lane >> 2, tg = lane & 3;
    int bm = blockIdx.x * 64, bn = blockIdx.y * 64;

    uint32_t asB = (uint32_t)__cvta_generic_to_shared(&As[0][0][0]);
    uint32_t bsB = (uint32_t)__cvta_generic_to_shared(&Bs[0][0][0]);

    float acc[2][4][4], snap[2][4][4];
#pragma unroll
    for (int i = 0; i < 2; i++)
#pragma unroll
        for (int j = 0; j < 4; j++)
#pragma unroll
            for (int q = 0; q < 4; q++) acc[i][j][q] = 0.f;

    auto load_tile = [&](int kt, int s) {
        int k0 = kt * 32;
        const float *Ap, *Bp;
        int la, lb, kl;
        if (k0 < 2 * HH) { Ap = Xp; la = 2 * HH; Bp = Wih; lb = 2 * HH; kl = k0; }
        else { Ap = Hp; la = HH; Bp = Whh; lb = HH; kl = k0 - 2 * HH; }
#pragma unroll
        for (int it = 0; it < 4; it++) {
            int id = tid + it * 128;
            int r = id >> 3, c = id & 7;
            cp16(asB + (((s * 64 + r) * LST) + c * 4) * 4,
                 Ap + (size_t)(bm + r) * la + kl + c * 4);
        }
#pragma unroll
        for (int it = 0; it < 4; it++) {
            int id = tid + it * 128;
            int r = id >> 3, c = id & 7;
            cp16(bsB + (((s * 64 + r) * LST) + c * 4) * 4,
                 Bp + (size_t)(bn + r) * lb + kl + c * 4);
        }
        CP_COMMIT;
    };

    const int NT = 48;
    const int KT1 = 32;
    load_tile(0, 0);
    for (int kt = 0; kt < NT; kt++) {
        if (kt + 1 < NT) { load_tile(kt + 1, (kt + 1) & 1); CP_WAIT1; }
        else { CP_WAIT0; }
        __syncthreads();
        int s = kt & 1;
#pragma unroll
        for (int kk = 0; kk < 32; kk += 8) {
            uint32_t a[2][4], b[4][2];
#pragma unroll
            for (int i = 0; i < 2; i++) {
                const float* r0 = &As[s][wm * 32 + i * 16 + gr][kk];
                a[i][0] = ldtf(r0 + tg);
                a[i][1] = ldtf(r0 + 8 * LST + tg);
                a[i][2] = ldtf(r0 + tg + 4);
                a[i][3] = ldtf(r0 + 8 * LST + tg + 4);
            }
#pragma unroll
            for (int j = 0; j < 4; j++) {
                const float* c0 = &Bs[s][wn * 32 + j * 8 + gr][kk];
                b[j][0] = ldtf(c0 + tg);
                b[j][1] = ldtf(c0 + tg + 4);
            }
#pragma unroll
            for (int i = 0; i < 2; i++)
#pragma unroll
                for (int j = 0; j < 4; j++) mma_sync_tf32(acc[i][j], a[i], b[j]);
        }
        if (kt == KT1 - 1) {
#pragma unroll
            for (int i = 0; i < 2; i++)
#pragma unroll
                for (int j = 0; j < 4; j++)
#pragma unroll
                    for (int q = 0; q < 4; q++) snap[i][j][q] = acc[i][j][q];
        }
        __syncthreads();
    }

    const int N = 3 * HH;
#pragma unroll
    for (int i = 0; i < 2; i++) {
#pragma unroll
        for (int j = 0; j < 4; j++) {
            int row = bm + wm * 32 + i * 16 + gr;
            int col = bn + wn * 32 + j * 8 + tg * 2;
#pragma unroll
            for (int q = 0; q < 2; q++) {
                int cc = col + q;
                float gi0 = snap[i][j][q] + bih[cc];
                float gh0 = (acc[i][j][q] - snap[i][j][q]) + bhh[cc];
                float gi1 = snap[i][j][q + 2] + bih[cc];
                float gh1 = (acc[i][j][q + 2] - snap[i][j][q + 2]) + bhh[cc];
                g_gi[(size_t)row * N + cc] = gi0;
                g_gh[(size_t)row * N + cc] = gh0;
                g_gi[(size_t)(row + 8) * N + cc] = gi1;
                g_gh[(size_t)(row + 8) * N + cc] = gh1;
            }
        }
    }
}

// ---------------------------------------------------------------------------
// GRU gates: writes fp32 h_new (output) and fp16 copy (GEMM operand)
// ---------------------------------------------------------------------------
__global__ void __launch_bounds__(256) gate_kernel(const float* __restrict__ hprev,
                                                   float* __restrict__ out_h) {
    int idx = blockIdx.x * 256 + threadIdx.x;
    int b = idx >> 9, j = idx & 511;
    size_t gi0 = (size_t)b * 3 * HH + j;
    float i_r = g_gi[gi0], i_z = g_gi[gi0 + HH], i_n = g_gi[gi0 + 2 * HH];
    float h_r = g_gh[gi0], h_z = g_gh[gi0 + HH], h_n = g_gh[gi0 + 2 * HH];
    float r = 1.f / (1.f + expf(-(i_r + h_r)));
    float z = 1.f / (1.f + expf(-(i_z + h_z)));
    float n = tanhf(i_n + r * h_n);
    float h = hprev[idx];
    float hn = (1.f - z) * n + z * h;
    g_hnewh[idx] = __float2half_rn(hn);
    out_h[idx] = hn;
}

// ---------------------------------------------------------------------------
// log_softmax, two-pass (second read hits L2: whole logits = 51.5MB < L2)
// ---------------------------------------------------------------------------
__global__ void __launch_bounds__(512) lsesub_kernel(float* __restrict__ lg) {
    int b = blockIdx.x, t = threadIdx.x;
    int lane = t & 31, warp = t >> 5;
    __shared__ float sm_m[16], sm_s[16], s_lse[1];
    float* row = lg + (size_t)b * VV;
    float m = -1e30f, s = 0.f;
    for (int i = t; i < VV; i += 512) {
        float v = row[i];
        float nm = fmaxf(m, v);
        s = s * __expf(m - nm) + __expf(v - nm);
        m = nm;
    }
#pragma unroll
    for (int o = 16; o > 0; o >>= 1) {
        float om = __shfl_down_sync(0xffffffffu, m, o);
        float os = __shfl_down_sync(0xffffffffu, s, o);
        float nm = fmaxf(m, om);
        s = s * __expf(m - nm) + os * __expf(om - nm);
        m = nm;
    }
    if (lane == 0) { sm_m[warp] = m; sm_s[warp] = s; }
    __syncthreads();
    if (t == 0) {
        float M = sm_m[0], Ssum = sm_s[0];
#pragma unroll
        for (int w = 1; w < 16; w++) {
            float nm = fmaxf(M, sm_m[w]);
            Ssum = Ssum * __expf(M - nm) + sm_s[w] * __expf(sm_m[w] - nm);
            M = nm;
        }
        s_lse[0] = M + logf(Ssum);
    }
    __syncthreads();
    float lse = s_lse[0];
    for (int i = t; i < VV; i += 512) row[i] -= lse;
}

// ---------------------------------------------------------------------------
extern "C" void kernel_launch(void* const* d_in, const int* in_sizes, int n_in,
                              void* d_out, int out_size) {
    (void)in_sizes; (void)n_in; (void)out_size;
    const int*   tok    = (const int*)d_in[0];
    const float* hidden = (const float*)d_in[1];
    const float* enc    = (const float*)d_in[2];
    const float* emb    = (const float*)d_in[3];
    const float* attnW  = (const float*)d_in[4];
    // d_in[5] = attn_b: unused (cancels in softmax)
    const float* W_ih   = (const float*)d_in[6];
    const float* W_hh   = (const float*)d_in[7];
    const float* b_ih   = (const float*)d_in[8];
    const float* b_hh   = (const float*)d_in[9];
    const float* out_W  = (const float*)d_in[10];
    const float* out_b  = (const float*)d_in[11];

    float* out        = (float*)d_out;
    float* out_logits = out;
    float* out_h      = out + (size_t)BB * VV;
    float* out_attn   = out_h + (size_t)BB * HH;

    float* p_x;
    cudaGetSymbolAddress((void**)&p_x, g_x);

    cudaFuncSetAttribute(gemm_logits_f16, cudaFuncAttributeMaxDynamicSharedMemorySize,
                         61440);

    // 0) out_W -> fp16 (independent of everything else)
    {
        size_t total = (size_t)VV * HH;
        int blocks = (int)((total + 512 * 16 - 1) / (512 * 16));
        convw_kernel<<<blocks, 512>>>(out_W);
    }
    // 1) u = h @ attn_W (fp32)
    u_kernel<<<dim3(16, 4), 128>>>(hidden, attnW);
    // 2) softmax attention -> attn_weights + x
    attn_kernel<<<BB, 256>>>(enc, tok, emb, out_attn);
    // 3) fused GRU gate GEMM (pipelined tf32 mma.sync)
    gemm_gru<<<dim3(4, 24), 128>>>(p_x, hidden, W_ih, W_hh, b_ih, b_hh);
    // 4) gates -> h_new (fp32 out + fp16 operand)
    gate_kernel<<<(BB * HH) / 256, 256>>>(hidden, out_h);
    // 5) logits via fp16 mma.sync (out_W read once)
    gemm_logits_f16<<<(VV + 127) / 128, 512, 61440>>>(out_b, out_logits);
    // 6) log_softmax (two-pass; L2-resident second read)
    lsesub_kernel<<<BB, 512>>>(out_logits);
}